// round 13
// baseline (speedup 1.0000x reference)
#include <cuda_runtime.h>
#include <cuda_bf16.h>
#include <cstdint>

// ---------------------------------------------------------------------------
// v12 = v11 (565us) with Q,K,V merged into ONE triple-N GEMM pass:
// Wq->W, Wk->ks, Wv->qs staged ahead; A (xn) fragments loaded once feed
// three accumulator sets. Epilogue writes q/k/vT over the dead weight tiles.
// 152 persistent CTAs, 512 threads, 2 windows per iteration.
// ---------------------------------------------------------------------------

#define SMEM_BYTES 210432

#define OFF_XF    0        // f32  [128c][132t]  x residual
#define OFF_W     67584    // bf16 [128][136]    weight stage (Wq/Wo)
#define OFF_AB    102400   // bf16 [128][136]    xn -> vT -> outs_hi
#define OFF_QS    137216   // bf16 [128][136]    Wv -> q -> o -> y -> outs_lo
#define OFF_KS    172032   // bf16 [128][136]    Wk -> k -> conv weights
#define OFF_BIAS  206848   // f32 [896]

#define NWIN 4096
#define GRID 152

__device__ __align__(16) __nv_bfloat16 g_win[384 * 128];
__device__ __align__(16) __nv_bfloat16 g_wout[128 * 128];
__device__ __align__(16) __nv_bfloat16 g_wc[128 * 128];

__global__ void convert_weights_kernel(const float* __restrict__ win,
                                       const float* __restrict__ wout,
                                       const float* __restrict__ wc) {
    int i = blockIdx.x * blockDim.x + threadIdx.x;
    if (i < 384 * 128) g_win[i] = __float2bfloat16(win[i]);
    if (i < 128 * 128) {
        g_wout[i] = __float2bfloat16(wout[i]);
        g_wc[i] = __float2bfloat16(wc[i]);
    }
}

__device__ __forceinline__ void mma16816(float acc[4], uint32_t a0, uint32_t a1,
                                         uint32_t a2, uint32_t a3,
                                         uint32_t b0, uint32_t b1) {
    asm volatile(
        "mma.sync.aligned.m16n8k16.row.col.f32.bf16.bf16.f32 "
        "{%0,%1,%2,%3},{%4,%5,%6,%7},{%8,%9},{%0,%1,%2,%3};\n"
        : "+f"(acc[0]), "+f"(acc[1]), "+f"(acc[2]), "+f"(acc[3])
        : "r"(a0), "r"(a1), "r"(a2), "r"(a3), "r"(b0), "r"(b1));
}

__device__ __forceinline__ uint32_t packbf(float lo, float hi) {
    uint32_t r;
    asm("cvt.rn.bf16x2.f32 %0, %1, %2;" : "=r"(r) : "f"(hi), "f"(lo));
    return r;
}

__device__ __forceinline__ void ldsm4(uint32_t& r0, uint32_t& r1, uint32_t& r2,
                                      uint32_t& r3, uint32_t addr) {
    asm volatile("ldmatrix.sync.aligned.m8n8.x4.shared.b16 {%0,%1,%2,%3},[%4];"
                 : "=r"(r0), "=r"(r1), "=r"(r2), "=r"(r3) : "r"(addr));
}

__device__ __forceinline__ uint32_t su32(const void* p) {
    return (uint32_t)__cvta_generic_to_shared(p);
}

#define CPA16(dst, src) \
    asm volatile("cp.async.cg.shared.global [%0],[%1],16;" ::"r"(dst), "l"(src))
#define CPC() asm volatile("cp.async.commit_group;")
#define CPW(n) asm volatile("cp.async.wait_group %0;" ::"n"(n))

__device__ __forceinline__ void stage_w(const __nv_bfloat16* __restrict__ src,
                                        uint32_t dstu, int tid) {
#pragma unroll
    for (int it = 0; it < 4; it++) {
        int idx = it * 512 + tid;
        int row = idx >> 4, cq = idx & 15;
        CPA16(dstu + row * 272 + cq * 16, src + row * 128 + cq * 8);
    }
}

// issue cp.async for one window-pair of x into xf
__device__ __forceinline__ void load_x(const float* __restrict__ x, int w,
                                       uint32_t s_xf, int tid) {
    const int b = w >> 11;
    const int r = w & 2047;
    const int d0 = (r >> 7) * 4, h0 = ((r >> 3) & 15) * 4, wp = (r & 7) * 8;
    const float* xb = x + (size_t)b * 128 * 262144;
#pragma unroll
    for (int it = 0; it < 8; it++) {
        int idx = it * 512 + tid;
        int c = idx >> 5, rem = idx & 31;
        int win = rem >> 4, row = rem & 15;
        int dd = row >> 2, hh = row & 3;
        CPA16(s_xf + (c * 132 + win * 64 + row * 4) * 4,
              xb + (size_t)c * 262144 + (size_t)(d0 + dd) * 4096 +
                  (h0 + hh) * 64 + wp + win * 4);
    }
    CPC();
}

// D[32][32] += A[32 rows @Au][128] @ B[32 rows @Wu][128]^T, row stride 272B
__device__ __forceinline__ void gemm128(uint32_t Au, uint32_t Wu,
                                        float acc[2][4][4]) {
#pragma unroll
    for (int k = 0; k < 8; k++) {
        uint32_t a0, a1, a2, a3, e0, e1, e2, e3;
        uint32_t b0, b1, b2, b3, c0, c1, c2, c3;
        ldsm4(a0, a1, a2, a3, Au + k * 32);
        ldsm4(e0, e1, e2, e3, Au + 4352 + k * 32);
        ldsm4(b0, b1, b2, b3, Wu + k * 32);
        ldsm4(c0, c1, c2, c3, Wu + 4352 + k * 32);
        mma16816(acc[0][0], a0, a1, a2, a3, b0, b2);
        mma16816(acc[0][1], a0, a1, a2, a3, b1, b3);
        mma16816(acc[0][2], a0, a1, a2, a3, c0, c2);
        mma16816(acc[0][3], a0, a1, a2, a3, c1, c3);
        mma16816(acc[1][0], e0, e1, e2, e3, b0, b2);
        mma16816(acc[1][1], e0, e1, e2, e3, b1, b3);
        mma16816(acc[1][2], e0, e1, e2, e3, c0, c2);
        mma16816(acc[1][3], e0, e1, e2, e3, c1, c3);
    }
}

// triple-N GEMM: A loaded once per k-step, feeds three B matrices
__device__ __forceinline__ void gemm128_triple(uint32_t Au, uint32_t W1,
                                               uint32_t W2, uint32_t W3,
                                               float aq[2][4][4],
                                               float ak[2][4][4],
                                               float av[2][4][4]) {
#pragma unroll
    for (int k = 0; k < 8; k++) {
        uint32_t a0, a1, a2, a3, e0, e1, e2, e3;
        ldsm4(a0, a1, a2, a3, Au + k * 32);
        ldsm4(e0, e1, e2, e3, Au + 4352 + k * 32);
        {
            uint32_t b0, b1, b2, b3, c0, c1, c2, c3;
            ldsm4(b0, b1, b2, b3, W1 + k * 32);
            ldsm4(c0, c1, c2, c3, W1 + 4352 + k * 32);
            mma16816(aq[0][0], a0, a1, a2, a3, b0, b2);
            mma16816(aq[0][1], a0, a1, a2, a3, b1, b3);
            mma16816(aq[0][2], a0, a1, a2, a3, c0, c2);
            mma16816(aq[0][3], a0, a1, a2, a3, c1, c3);
            mma16816(aq[1][0], e0, e1, e2, e3, b0, b2);
            mma16816(aq[1][1], e0, e1, e2, e3, b1, b3);
            mma16816(aq[1][2], e0, e1, e2, e3, c0, c2);
            mma16816(aq[1][3], e0, e1, e2, e3, c1, c3);
        }
        {
            uint32_t b0, b1, b2, b3, c0, c1, c2, c3;
            ldsm4(b0, b1, b2, b3, W2 + k * 32);
            ldsm4(c0, c1, c2, c3, W2 + 4352 + k * 32);
            mma16816(ak[0][0], a0, a1, a2, a3, b0, b2);
            mma16816(ak[0][1], a0, a1, a2, a3, b1, b3);
            mma16816(ak[0][2], a0, a1, a2, a3, c0, c2);
            mma16816(ak[0][3], a0, a1, a2, a3, c1, c3);
            mma16816(ak[1][0], e0, e1, e2, e3, b0, b2);
            mma16816(ak[1][1], e0, e1, e2, e3, b1, b3);
            mma16816(ak[1][2], e0, e1, e2, e3, c0, c2);
            mma16816(ak[1][3], e0, e1, e2, e3, c1, c3);
        }
        {
            uint32_t b0, b1, b2, b3, c0, c1, c2, c3;
            ldsm4(b0, b1, b2, b3, W3 + k * 32);
            ldsm4(c0, c1, c2, c3, W3 + 4352 + k * 32);
            mma16816(av[0][0], a0, a1, a2, a3, b0, b2);
            mma16816(av[0][1], a0, a1, a2, a3, b1, b3);
            mma16816(av[0][2], a0, a1, a2, a3, c0, c2);
            mma16816(av[0][3], a0, a1, a2, a3, c1, c3);
            mma16816(av[1][0], e0, e1, e2, e3, b0, b2);
            mma16816(av[1][1], e0, e1, e2, e3, b1, b3);
            mma16816(av[1][2], e0, e1, e2, e3, c0, c2);
            mma16816(av[1][3], e0, e1, e2, e3, c1, c3);
        }
    }
}

__global__ void __launch_bounds__(512, 1)
fused_wsa3d_kernel(const float* __restrict__ x,
                   const float* __restrict__ ln_g, const float* __restrict__ ln_b,
                   const float* __restrict__ in_b, const float* __restrict__ out_b,
                   const float* __restrict__ conv_b,
                   float* __restrict__ out) {
    extern __shared__ char sm[];
    float* xf = (float*)(sm + OFF_XF);                      // [128c][132t]
    __nv_bfloat16* ab = (__nv_bfloat16*)(sm + OFF_AB);
    __nv_bfloat16* qs = (__nv_bfloat16*)(sm + OFF_QS);
    __nv_bfloat16* ks_ = (__nv_bfloat16*)(sm + OFF_KS);
    float* bias = (float*)(sm + OFF_BIAS);
    float* outs_lo = (float*)(sm + OFF_QS);   // c 0..63   [64][132]
    float* outs_hi = (float*)(sm + OFF_AB);   // c 64..127 [64][132]

    const int tid = threadIdx.x;
    const int warp = tid >> 5, lane = tid & 31;
    const int g = lane >> 2, q2 = (lane & 3) * 2;
    const int lane16 = lane & 15, laneh = lane >> 4;
    const int mq = warp & 3, nq = warp >> 2;

    const uint32_t s_xf = su32(xf);
    const uint32_t s_ab = su32(ab);
    const uint32_t s_qs = su32(qs);
    const uint32_t s_ks = su32(ks_);
    const uint32_t s_w = su32(sm + OFF_W);
    const uint32_t off136 = (uint32_t)(lane16 * 272 + laneh * 16);

    const uint32_t Aab = s_ab + mq * 32 * 272 + off136;
    const uint32_t Aqs = s_qs + mq * 32 * 272 + off136;
    const uint32_t Wn = s_w + nq * 32 * 272 + off136;
    const uint32_t Wk = s_ks + nq * 32 * 272 + off136;
    const uint32_t Wv = s_qs + nq * 32 * 272 + off136;

    // ---- biases once ----
    for (int i = tid; i < 896; i += 512) {
        float v;
        if (i < 128)      v = ln_g[i];
        else if (i < 256) v = ln_b[i - 128];
        else if (i < 640) v = in_b[i - 256];
        else if (i < 768) v = out_b[i - 640];
        else              v = conv_b[i - 768];
        bias[i] = v;
    }

    // ---- first x window + Wq(->W) + Wk(->ks) ----
    load_x(x, blockIdx.x, s_xf, tid);            // group: x
    stage_w(g_win, s_w, tid);
    stage_w(g_win + 16384, s_ks, tid);
    CPC();                                       // group: Wq+Wk
    CPW(1);                                      // x done
    __syncthreads();

    for (int w = blockIdx.x; w < NWIN; w += GRID) {
        const int b = w >> 11;
        const int r = w & 2047;
        const int d0 = (r >> 7) * 4, h0 = ((r >> 3) & 15) * 4, wp = (r & 7) * 8;

        // ---- issue Wv -> qs (qs dead until q epilogue) ----
        stage_w(g_win + 32768, s_qs, tid);
        CPC();

        // ---- LayerNorm (4 threads / token) ----
        {
            int t = tid >> 2, j = tid & 3;
            float s = 0.f, s2 = 0.f;
#pragma unroll
            for (int i = 0; i < 32; i++) {
                float v = xf[(j + 4 * i) * 132 + t];
                s += v; s2 += v * v;
            }
            s  += __shfl_xor_sync(0xffffffffu, s, 1);
            s  += __shfl_xor_sync(0xffffffffu, s, 2);
            s2 += __shfl_xor_sync(0xffffffffu, s2, 1);
            s2 += __shfl_xor_sync(0xffffffffu, s2, 2);
            float mu = s * (1.f / 128.f);
            float var = s2 * (1.f / 128.f) - mu * mu;
            float rstd = rsqrtf(var + 1e-5f);
#pragma unroll
            for (int i = 0; i < 32; i++) {
                int c = j + 4 * i;
                float v = (xf[c * 132 + t] - mu) * rstd * bias[c] + bias[128 + c];
                ab[t * 136 + c] = __float2bfloat16(v);
            }
        }
        CPW(0);          // Wq + Wk + Wv staged
        __syncthreads();

        // ---- Q,K,V = xn @ {Wq,Wk,Wv} (triple) ; Wo staged under epilogue ----
        {
            float aq[2][4][4] = {}, ak[2][4][4] = {}, av[2][4][4] = {};
            gemm128_triple(Aab, Wn, Wk, Wv, aq, ak, av);
            __syncthreads();               // all W + xn reads done
            stage_w(g_wout, s_w, tid);     // Wo over Wq
            CPC();
#pragma unroll
            for (int m = 0; m < 2; m++)
#pragma unroll
                for (int nt = 0; nt < 4; nt++) {
                    int cc = nq * 32 + nt * 8 + q2;
                    int ra = mq * 32 + m * 16 + g, rb = ra + 8;
                    float bq0 = bias[256 + cc], bq1 = bias[256 + cc + 1];
                    float bk0 = bias[384 + cc], bk1 = bias[384 + cc + 1];
                    float bv0 = bias[512 + cc], bv1 = bias[512 + cc + 1];
                    *(uint32_t*)(qs + ra * 136 + cc) = packbf(aq[m][nt][0] + bq0, aq[m][nt][1] + bq1);
                    *(uint32_t*)(qs + rb * 136 + cc) = packbf(aq[m][nt][2] + bq0, aq[m][nt][3] + bq1);
                    *(uint32_t*)(ks_ + ra * 136 + cc) = packbf(ak[m][nt][0] + bk0, ak[m][nt][1] + bk1);
                    *(uint32_t*)(ks_ + rb * 136 + cc) = packbf(ak[m][nt][2] + bk0, ak[m][nt][3] + bk1);
                    ab[cc * 136 + ra]       = __float2bfloat16(av[m][nt][0] + bv0);
                    ab[(cc + 1) * 136 + ra] = __float2bfloat16(av[m][nt][1] + bv1);
                    ab[cc * 136 + rb]       = __float2bfloat16(av[m][nt][2] + bv0);
                    ab[(cc + 1) * 136 + rb] = __float2bfloat16(av[m][nt][3] + bv1);
                }
        }
        CPW(0);  // Wo staged
        __syncthreads();

        // ---- Attention: 32 tasks (win,head,mtile), 2 per warp ----
#pragma unroll 1
        for (int ti = 0; ti < 2; ti++) {
            const int task = warp + ti * 16;
            const int win = task >> 4;
            const int head = (task >> 2) & 3;
            const int mt = task & 3;
            const uint32_t Aq = s_qs + (win * 64 + mt * 16) * 272 + off136 + head * 64;
            const uint32_t Bk = s_ks + (win * 64) * 272 + off136 + head * 64;

            float P[8][4] = {};
#pragma unroll
            for (int k2 = 0; k2 < 2; k2++) {
                uint32_t a0, a1, a2, a3;
                ldsm4(a0, a1, a2, a3, Aq + k2 * 32);
#pragma unroll
                for (int p = 0; p < 4; p++) {
                    uint32_t b0, b1, b2, b3;
                    ldsm4(b0, b1, b2, b3, Bk + p * 4352 + k2 * 32);
                    mma16816(P[2 * p], a0, a1, a2, a3, b0, b2);
                    mma16816(P[2 * p + 1], a0, a1, a2, a3, b1, b3);
                }
            }
            const float scale = 0.17677669529663687f;  // 1/sqrt(32)
            float mA = -1e30f, mB = -1e30f;
#pragma unroll
            for (int nt = 0; nt < 8; nt++) {
                mA = fmaxf(mA, fmaxf(P[nt][0], P[nt][1]));
                mB = fmaxf(mB, fmaxf(P[nt][2], P[nt][3]));
            }
            mA = fmaxf(mA, __shfl_xor_sync(0xffffffffu, mA, 1));
            mA = fmaxf(mA, __shfl_xor_sync(0xffffffffu, mA, 2));
            mB = fmaxf(mB, __shfl_xor_sync(0xffffffffu, mB, 1));
            mB = fmaxf(mB, __shfl_xor_sync(0xffffffffu, mB, 2));
            float sA = 0.f, sB = 0.f;
#pragma unroll
            for (int nt = 0; nt < 8; nt++) {
                float e0 = __expf((P[nt][0] - mA) * scale);
                float e1 = __expf((P[nt][1] - mA) * scale);
                float e2 = __expf((P[nt][2] - mB) * scale);
                float e3 = __expf((P[nt][3] - mB) * scale);
                P[nt][0] = e0; P[nt][1] = e1; P[nt][2] = e2; P[nt][3] = e3;
                sA += e0 + e1; sB += e2 + e3;
            }
            sA += __shfl_xor_sync(0xffffffffu, sA, 1);
            sA += __shfl_xor_sync(0xffffffffu, sA, 2);
            sB += __shfl_xor_sync(0xffffffffu, sB, 1);
            sB += __shfl_xor_sync(0xffffffffu, sB, 2);
            float iA = 1.f / sA, iB = 1.f / sB;

            const uint32_t Bv = s_ab + (head * 32) * 272 + off136 + win * 128;
            float accO[4][4] = {};
#pragma unroll
            for (int ks = 0; ks < 4; ks++) {
                uint32_t a0 = packbf(P[2 * ks][0] * iA, P[2 * ks][1] * iA);
                uint32_t a1 = packbf(P[2 * ks][2] * iB, P[2 * ks][3] * iB);
                uint32_t a2 = packbf(P[2 * ks + 1][0] * iA, P[2 * ks + 1][1] * iA);
                uint32_t a3 = packbf(P[2 * ks + 1][2] * iB, P[2 * ks + 1][3] * iB);
                uint32_t b0, b1, b2, b3;
                ldsm4(b0, b1, b2, b3, Bv + ks * 32);
                mma16816(accO[0], a0, a1, a2, a3, b0, b2);
                mma16816(accO[1], a0, a1, a2, a3, b1, b3);
                ldsm4(b0, b1, b2, b3, Bv + 4352 + ks * 32);
                mma16816(accO[2], a0, a1, a2, a3, b0, b2);
                mma16816(accO[3], a0, a1, a2, a3, b1, b3);
            }
            int ta = win * 64 + mt * 16 + g, tb = ta + 8;
#pragma unroll
            for (int nt = 0; nt < 4; nt++) {
                int cc = head * 32 + nt * 8 + q2;
                *(uint32_t*)(qs + ta * 136 + cc) = packbf(accO[nt][0], accO[nt][1]);
                *(uint32_t*)(qs + tb * 136 + cc) = packbf(accO[nt][2], accO[nt][3]);
            }
        }
        __syncthreads();

        // ---- out_proj (+residual) -> y (bf16, qs) ; conv W into ks ----
        stage_w(g_wc, s_ks, tid);
        CPC();
        {
            float acc[2][4][4] = {};
            gemm128(Aqs, Wn, acc);  // o @ Wo
            __syncthreads();        // o + Wo reads done
#pragma unroll
            for (int m = 0; m < 2; m++)
#pragma unroll
                for (int nt = 0; nt < 4; nt++) {
                    int cc = nq * 32 + nt * 8 + q2;
                    int ra = mq * 32 + m * 16 + g, rb = ra + 8;
                    float y00 = acc[m][nt][0] + bias[640 + cc]     + xf[cc * 132 + ra];
                    float y01 = acc[m][nt][1] + bias[640 + cc + 1] + xf[(cc + 1) * 132 + ra];
                    float y10 = acc[m][nt][2] + bias[640 + cc]     + xf[cc * 132 + rb];
                    float y11 = acc[m][nt][3] + bias[640 + cc + 1] + xf[(cc + 1) * 132 + rb];
                    *(uint32_t*)(qs + ra * 136 + cc) = packbf(y00, y01);
                    *(uint32_t*)(qs + rb * 136 + cc) = packbf(y10, y11);
                }
        }
        CPW(0);  // conv W ready
        __syncthreads();

        // ---- conv: single GEMM y @ Wc ----
        {
            float acc[2][4][4] = {};
            gemm128(Aqs, Wk, acc);
            __syncthreads();  // all qs + Wc reads done -> outs overlay safe

            // epilogue: outs = acc + conv_b + x, into dead qs/ab (f32 [c][132])
            float* obase = (nq < 2) ? outs_lo : outs_hi;
            int csub = (nq < 2) ? 0 : 64;
#pragma unroll
            for (int m = 0; m < 2; m++)
#pragma unroll
                for (int nt = 0; nt < 4; nt++) {
                    int cc = nq * 32 + nt * 8 + q2;
                    int c0 = cc - csub;
                    int ra = mq * 32 + m * 16 + g, rb = ra + 8;
                    obase[c0 * 132 + ra]       = acc[m][nt][0] + bias[768 + cc]     + xf[cc * 132 + ra];
                    obase[(c0 + 1) * 132 + ra] = acc[m][nt][1] + bias[768 + cc + 1] + xf[(cc + 1) * 132 + ra];
                    obase[c0 * 132 + rb]       = acc[m][nt][2] + bias[768 + cc]     + xf[cc * 132 + rb];
                    obase[(c0 + 1) * 132 + rb] = acc[m][nt][3] + bias[768 + cc + 1] + xf[(cc + 1) * 132 + rb];
                }
        }
        __syncthreads();  // outs visible; xf fully read -> prefetch can land

        // ---- prefetch next window + Wq + Wk BEFORE the store ----
        const bool more = (w + GRID < NWIN);
        if (more) {
            load_x(x, w + GRID, s_xf, tid);          // group: x
            stage_w(g_win, s_w, tid);
            stage_w(g_win + 16384, s_ks, tid);
            CPC();                                   // group: Wq+Wk
        }

        // ---- store from outs (qs/ab overlays) ----
        float* ob = out + (size_t)b * 128 * 262144;
#pragma unroll
        for (int it = 0; it < 4; it++) {
            int idx = it * 512 + tid;
            int c = idx >> 5, rem = idx & 31;
            int win = rem >> 4, row = rem & 15;
            int dd = row >> 2, hh = row & 3;
            *(float4*)(ob + (size_t)c * 262144 + (size_t)(d0 + dd) * 4096 +
                       (h0 + hh) * 64 + wp + win * 4) =
                *(float4*)(outs_lo + c * 132 + win * 64 + row * 4);
        }
#pragma unroll
        for (int it = 4; it < 8; it++) {
            int idx = it * 512 + tid;
            int c = idx >> 5, rem = idx & 31;
            int win = rem >> 4, row = rem & 15;
            int dd = row >> 2, hh = row & 3;
            *(float4*)(ob + (size_t)c * 262144 + (size_t)(d0 + dd) * 4096 +
                       (h0 + hh) * 64 + wp + win * 4) =
                *(float4*)(outs_hi + (c - 64) * 132 + win * 64 + row * 4);
        }
        if (more) CPW(1);  // next x done (Wq+Wk waited after next LN)
        __syncthreads();   // outs reads done; xf/qs ready for next iter
    }
}

extern "C" void kernel_launch(void* const* d_in, const int* in_sizes, int n_in,
                              void* d_out, int out_size) {
    const float* x      = (const float*)d_in[0];
    const float* ln_g   = (const float*)d_in[1];
    const float* ln_b   = (const float*)d_in[2];
    const float* in_b   = (const float*)d_in[4];
    const float* out_w  = (const float*)d_in[5];
    const float* out_b  = (const float*)d_in[6];
    const float* conv_w = (const float*)d_in[7];
    const float* conv_b = (const float*)d_in[8];
    const float* in_w   = (const float*)d_in[3];
    float* out = (float*)d_out;

    convert_weights_kernel<<<192, 256>>>(in_w, out_w, conv_w);

    cudaFuncSetAttribute(fused_wsa3d_kernel,
                         cudaFuncAttributeMaxDynamicSharedMemorySize, SMEM_BYTES);
    fused_wsa3d_kernel<<<GRID, 512, SMEM_BYTES>>>(x, ln_g, ln_b, in_b, out_b,
                                                  conv_b, out);
}

// round 14
// speedup vs baseline: 1.0167x; 1.0167x over previous
#include <cuda_runtime.h>
#include <cuda_bf16.h>
#include <cstdint>

// ---------------------------------------------------------------------------
// v13 = v11 (best: 565us, dual-QK) + LayerNorm micro-opt:
//   - xf read once into registers (vv[32], LN-scoped)
//   - channel mapping j*32+i: conflict-free reads, packed uint32 stores
// 152 persistent CTAs, 512 threads, 2 windows per iteration.
// (R13 lesson: >64 accumulator regs per phase spills; triple-merge reverted.)
// ---------------------------------------------------------------------------

#define SMEM_BYTES 210432

#define OFF_XF    0        // f32  [128c][132t]  x residual
#define OFF_W     67584    // bf16 [128][136]    weight stage (Wq/Wv/Wo)
#define OFF_AB    102400   // bf16 [128][136]    xn -> vT -> outs_hi
#define OFF_QS    137216   // bf16 [128][136]    q -> o -> y -> outs_lo
#define OFF_KS    172032   // bf16 [128][136]    Wk -> k -> conv weights
#define OFF_BIAS  206848   // f32 [896]

#define NWIN 4096
#define GRID 152

__device__ __align__(16) __nv_bfloat16 g_win[384 * 128];
__device__ __align__(16) __nv_bfloat16 g_wout[128 * 128];
__device__ __align__(16) __nv_bfloat16 g_wc[128 * 128];

__global__ void convert_weights_kernel(const float* __restrict__ win,
                                       const float* __restrict__ wout,
                                       const float* __restrict__ wc) {
    int i = blockIdx.x * blockDim.x + threadIdx.x;
    if (i < 384 * 128) g_win[i] = __float2bfloat16(win[i]);
    if (i < 128 * 128) {
        g_wout[i] = __float2bfloat16(wout[i]);
        g_wc[i] = __float2bfloat16(wc[i]);
    }
}

__device__ __forceinline__ void mma16816(float acc[4], uint32_t a0, uint32_t a1,
                                         uint32_t a2, uint32_t a3,
                                         uint32_t b0, uint32_t b1) {
    asm volatile(
        "mma.sync.aligned.m16n8k16.row.col.f32.bf16.bf16.f32 "
        "{%0,%1,%2,%3},{%4,%5,%6,%7},{%8,%9},{%0,%1,%2,%3};\n"
        : "+f"(acc[0]), "+f"(acc[1]), "+f"(acc[2]), "+f"(acc[3])
        : "r"(a0), "r"(a1), "r"(a2), "r"(a3), "r"(b0), "r"(b1));
}

__device__ __forceinline__ uint32_t packbf(float lo, float hi) {
    uint32_t r;
    asm("cvt.rn.bf16x2.f32 %0, %1, %2;" : "=r"(r) : "f"(hi), "f"(lo));
    return r;
}

__device__ __forceinline__ void ldsm4(uint32_t& r0, uint32_t& r1, uint32_t& r2,
                                      uint32_t& r3, uint32_t addr) {
    asm volatile("ldmatrix.sync.aligned.m8n8.x4.shared.b16 {%0,%1,%2,%3},[%4];"
                 : "=r"(r0), "=r"(r1), "=r"(r2), "=r"(r3) : "r"(addr));
}

__device__ __forceinline__ uint32_t su32(const void* p) {
    return (uint32_t)__cvta_generic_to_shared(p);
}

#define CPA16(dst, src) \
    asm volatile("cp.async.cg.shared.global [%0],[%1],16;" ::"r"(dst), "l"(src))
#define CPC() asm volatile("cp.async.commit_group;")
#define CPW(n) asm volatile("cp.async.wait_group %0;" ::"n"(n))

__device__ __forceinline__ void stage_w(const __nv_bfloat16* __restrict__ src,
                                        uint32_t dstu, int tid) {
#pragma unroll
    for (int it = 0; it < 4; it++) {
        int idx = it * 512 + tid;
        int row = idx >> 4, cq = idx & 15;
        CPA16(dstu + row * 272 + cq * 16, src + row * 128 + cq * 8);
    }
}

// issue cp.async for one window-pair of x into xf
__device__ __forceinline__ void load_x(const float* __restrict__ x, int w,
                                       uint32_t s_xf, int tid) {
    const int b = w >> 11;
    const int r = w & 2047;
    const int d0 = (r >> 7) * 4, h0 = ((r >> 3) & 15) * 4, wp = (r & 7) * 8;
    const float* xb = x + (size_t)b * 128 * 262144;
#pragma unroll
    for (int it = 0; it < 8; it++) {
        int idx = it * 512 + tid;
        int c = idx >> 5, rem = idx & 31;
        int win = rem >> 4, row = rem & 15;
        int dd = row >> 2, hh = row & 3;
        CPA16(s_xf + (c * 132 + win * 64 + row * 4) * 4,
              xb + (size_t)c * 262144 + (size_t)(d0 + dd) * 4096 +
                  (h0 + hh) * 64 + wp + win * 4);
    }
    CPC();
}

// D[32][32] += A[32 rows @Au][128] @ B[32 rows @Wu][128]^T, row stride 272B
__device__ __forceinline__ void gemm128(uint32_t Au, uint32_t Wu,
                                        float acc[2][4][4]) {
#pragma unroll
    for (int k = 0; k < 8; k++) {
        uint32_t a0, a1, a2, a3, e0, e1, e2, e3;
        uint32_t b0, b1, b2, b3, c0, c1, c2, c3;
        ldsm4(a0, a1, a2, a3, Au + k * 32);
        ldsm4(e0, e1, e2, e3, Au + 4352 + k * 32);
        ldsm4(b0, b1, b2, b3, Wu + k * 32);
        ldsm4(c0, c1, c2, c3, Wu + 4352 + k * 32);
        mma16816(acc[0][0], a0, a1, a2, a3, b0, b2);
        mma16816(acc[0][1], a0, a1, a2, a3, b1, b3);
        mma16816(acc[0][2], a0, a1, a2, a3, c0, c2);
        mma16816(acc[0][3], a0, a1, a2, a3, c1, c3);
        mma16816(acc[1][0], e0, e1, e2, e3, b0, b2);
        mma16816(acc[1][1], e0, e1, e2, e3, b1, b3);
        mma16816(acc[1][2], e0, e1, e2, e3, c0, c2);
        mma16816(acc[1][3], e0, e1, e2, e3, c1, c3);
    }
}

// dual-N GEMM: A loaded once, feeds two B matrices (Wq and Wk)
__device__ __forceinline__ void gemm128_dual(uint32_t Au, uint32_t W1,
                                             uint32_t W2, float aq[2][4][4],
                                             float ak[2][4][4]) {
#pragma unroll
    for (int k = 0; k < 8; k++) {
        uint32_t a0, a1, a2, a3, e0, e1, e2, e3;
        ldsm4(a0, a1, a2, a3, Au + k * 32);
        ldsm4(e0, e1, e2, e3, Au + 4352 + k * 32);
        {
            uint32_t b0, b1, b2, b3, c0, c1, c2, c3;
            ldsm4(b0, b1, b2, b3, W1 + k * 32);
            ldsm4(c0, c1, c2, c3, W1 + 4352 + k * 32);
            mma16816(aq[0][0], a0, a1, a2, a3, b0, b2);
            mma16816(aq[0][1], a0, a1, a2, a3, b1, b3);
            mma16816(aq[0][2], a0, a1, a2, a3, c0, c2);
            mma16816(aq[0][3], a0, a1, a2, a3, c1, c3);
            mma16816(aq[1][0], e0, e1, e2, e3, b0, b2);
            mma16816(aq[1][1], e0, e1, e2, e3, b1, b3);
            mma16816(aq[1][2], e0, e1, e2, e3, c0, c2);
            mma16816(aq[1][3], e0, e1, e2, e3, c1, c3);
        }
        {
            uint32_t b0, b1, b2, b3, c0, c1, c2, c3;
            ldsm4(b0, b1, b2, b3, W2 + k * 32);
            ldsm4(c0, c1, c2, c3, W2 + 4352 + k * 32);
            mma16816(ak[0][0], a0, a1, a2, a3, b0, b2);
            mma16816(ak[0][1], a0, a1, a2, a3, b1, b3);
            mma16816(ak[0][2], a0, a1, a2, a3, c0, c2);
            mma16816(ak[0][3], a0, a1, a2, a3, c1, c3);
            mma16816(ak[1][0], e0, e1, e2, e3, b0, b2);
            mma16816(ak[1][1], e0, e1, e2, e3, b1, b3);
            mma16816(ak[1][2], e0, e1, e2, e3, c0, c2);
            mma16816(ak[1][3], e0, e1, e2, e3, c1, c3);
        }
    }
}

__global__ void __launch_bounds__(512, 1)
fused_wsa3d_kernel(const float* __restrict__ x,
                   const float* __restrict__ ln_g, const float* __restrict__ ln_b,
                   const float* __restrict__ in_b, const float* __restrict__ out_b,
                   const float* __restrict__ conv_b,
                   float* __restrict__ out) {
    extern __shared__ char sm[];
    float* xf = (float*)(sm + OFF_XF);                      // [128c][132t]
    __nv_bfloat16* ab = (__nv_bfloat16*)(sm + OFF_AB);
    __nv_bfloat16* qs = (__nv_bfloat16*)(sm + OFF_QS);
    __nv_bfloat16* ks_ = (__nv_bfloat16*)(sm + OFF_KS);
    float* bias = (float*)(sm + OFF_BIAS);
    float* outs_lo = (float*)(sm + OFF_QS);   // c 0..63   [64][132]
    float* outs_hi = (float*)(sm + OFF_AB);   // c 64..127 [64][132]

    const int tid = threadIdx.x;
    const int warp = tid >> 5, lane = tid & 31;
    const int g = lane >> 2, q2 = (lane & 3) * 2;
    const int lane16 = lane & 15, laneh = lane >> 4;
    const int mq = warp & 3, nq = warp >> 2;

    const uint32_t s_xf = su32(xf);
    const uint32_t s_ab = su32(ab);
    const uint32_t s_qs = su32(qs);
    const uint32_t s_ks = su32(ks_);
    const uint32_t s_w = su32(sm + OFF_W);
    const uint32_t off136 = (uint32_t)(lane16 * 272 + laneh * 16);

    const uint32_t Aab = s_ab + mq * 32 * 272 + off136;
    const uint32_t Aqs = s_qs + mq * 32 * 272 + off136;
    const uint32_t Wn = s_w + nq * 32 * 272 + off136;
    const uint32_t Wk = s_ks + nq * 32 * 272 + off136;

    // ---- biases once ----
    for (int i = tid; i < 896; i += 512) {
        float v;
        if (i < 128)      v = ln_g[i];
        else if (i < 256) v = ln_b[i - 128];
        else if (i < 640) v = in_b[i - 256];
        else if (i < 768) v = out_b[i - 640];
        else              v = conv_b[i - 768];
        bias[i] = v;
    }

    // ---- first x window + Wq(->W) + Wk(->ks) ----
    load_x(x, blockIdx.x, s_xf, tid);            // group: x
    stage_w(g_win, s_w, tid);
    stage_w(g_win + 16384, s_ks, tid);
    CPC();                                       // group: Wq+Wk
    CPW(1);                                      // x done
    __syncthreads();

    for (int w = blockIdx.x; w < NWIN; w += GRID) {
        const int b = w >> 11;
        const int r = w & 2047;
        const int d0 = (r >> 7) * 4, h0 = ((r >> 3) & 15) * 4, wp = (r & 7) * 8;

        // ---- LayerNorm (4 threads / token; xf read once; packed stores) ----
        {
            int t = tid >> 2, j = tid & 3;
            float vv[32];
            float s = 0.f, s2 = 0.f;
#pragma unroll
            for (int i = 0; i < 32; i++) {
                vv[i] = xf[(j * 32 + i) * 132 + t];
                s += vv[i]; s2 += vv[i] * vv[i];
            }
            s  += __shfl_xor_sync(0xffffffffu, s, 1);
            s  += __shfl_xor_sync(0xffffffffu, s, 2);
            s2 += __shfl_xor_sync(0xffffffffu, s2, 1);
            s2 += __shfl_xor_sync(0xffffffffu, s2, 2);
            float mu = s * (1.f / 128.f);
            float var = s2 * (1.f / 128.f) - mu * mu;
            float rstd = rsqrtf(var + 1e-5f);
#pragma unroll
            for (int m = 0; m < 16; m++) {
                int c = j * 32 + 2 * m;
                float v0 = (vv[2 * m] - mu) * rstd * bias[c] + bias[128 + c];
                float v1 = (vv[2 * m + 1] - mu) * rstd * bias[c + 1] + bias[128 + c + 1];
                *(uint32_t*)(ab + t * 136 + c) = packbf(v0, v1);
            }
        }
        CPW(0);          // Wq + Wk staged
        __syncthreads();

        // ---- Q,K = xn @ {Wq,Wk} (dual) ; Wv staged under epilogue ----
        {
            float aq[2][4][4] = {}, ak[2][4][4] = {};
            gemm128_dual(Aab, Wn, Wk, aq, ak);
            __syncthreads();                    // Wq + Wk reads done
            stage_w(g_win + 32768, s_w, tid);   // issue Wv
            CPC();
#pragma unroll
            for (int m = 0; m < 2; m++)
#pragma unroll
                for (int nt = 0; nt < 4; nt++) {
                    int cc = nq * 32 + nt * 8 + q2;
                    int ra = mq * 32 + m * 16 + g, rb = ra + 8;
                    float bq0 = bias[256 + cc], bq1 = bias[256 + cc + 1];
                    float bk0 = bias[384 + cc], bk1 = bias[384 + cc + 1];
                    *(uint32_t*)(qs + ra * 136 + cc) = packbf(aq[m][nt][0] + bq0, aq[m][nt][1] + bq1);
                    *(uint32_t*)(qs + rb * 136 + cc) = packbf(aq[m][nt][2] + bq0, aq[m][nt][3] + bq1);
                    *(uint32_t*)(ks_ + ra * 136 + cc) = packbf(ak[m][nt][0] + bk0, ak[m][nt][1] + bk1);
                    *(uint32_t*)(ks_ + rb * 136 + cc) = packbf(ak[m][nt][2] + bk0, ak[m][nt][3] + bk1);
                }
        }
        CPW(0);
        __syncthreads();

        // ---- V = xn @ Wv -> vT into ab ; Wo staged under epilogue ----
        {
            float acc[2][4][4] = {};
            gemm128(Aab, Wn, acc);
            __syncthreads();               // Wv reads + all xn reads done
            stage_w(g_wout, s_w, tid);
            CPC();
#pragma unroll
            for (int m = 0; m < 2; m++)
#pragma unroll
                for (int nt = 0; nt < 4; nt++) {
                    int cc = nq * 32 + nt * 8 + q2;
                    int ra = mq * 32 + m * 16 + g, rb = ra + 8;
                    float b0 = bias[512 + cc], b1 = bias[512 + cc + 1];
                    ab[cc * 136 + ra]       = __float2bfloat16(acc[m][nt][0] + b0);
                    ab[(cc + 1) * 136 + ra] = __float2bfloat16(acc[m][nt][1] + b1);
                    ab[cc * 136 + rb]       = __float2bfloat16(acc[m][nt][2] + b0);
                    ab[(cc + 1) * 136 + rb] = __float2bfloat16(acc[m][nt][3] + b1);
                }
        }
        __syncthreads();  // vT visible (Wo in flight)

        // ---- Attention: 32 tasks (win,head,mtile), 2 per warp ----
#pragma unroll 1
        for (int ti = 0; ti < 2; ti++) {
            const int task = warp + ti * 16;
            const int win = task >> 4;
            const int head = (task >> 2) & 3;
            const int mt = task & 3;
            const uint32_t Aq = s_qs + (win * 64 + mt * 16) * 272 + off136 + head * 64;
            const uint32_t Bk = s_ks + (win * 64) * 272 + off136 + head * 64;

            float P[8][4] = {};
#pragma unroll
            for (int k2 = 0; k2 < 2; k2++) {
                uint32_t a0, a1, a2, a3;
                ldsm4(a0, a1, a2, a3, Aq + k2 * 32);
#pragma unroll
                for (int p = 0; p < 4; p++) {
                    uint32_t b0, b1, b2, b3;
                    ldsm4(b0, b1, b2, b3, Bk + p * 4352 + k2 * 32);
                    mma16816(P[2 * p], a0, a1, a2, a3, b0, b2);
                    mma16816(P[2 * p + 1], a0, a1, a2, a3, b1, b3);
                }
            }
            const float scale = 0.17677669529663687f;  // 1/sqrt(32)
            float mA = -1e30f, mB = -1e30f;
#pragma unroll
            for (int nt = 0; nt < 8; nt++) {
                mA = fmaxf(mA, fmaxf(P[nt][0], P[nt][1]));
                mB = fmaxf(mB, fmaxf(P[nt][2], P[nt][3]));
            }
            mA = fmaxf(mA, __shfl_xor_sync(0xffffffffu, mA, 1));
            mA = fmaxf(mA, __shfl_xor_sync(0xffffffffu, mA, 2));
            mB = fmaxf(mB, __shfl_xor_sync(0xffffffffu, mB, 1));
            mB = fmaxf(mB, __shfl_xor_sync(0xffffffffu, mB, 2));
            float sA = 0.f, sB = 0.f;
#pragma unroll
            for (int nt = 0; nt < 8; nt++) {
                float e0 = __expf((P[nt][0] - mA) * scale);
                float e1 = __expf((P[nt][1] - mA) * scale);
                float e2 = __expf((P[nt][2] - mB) * scale);
                float e3 = __expf((P[nt][3] - mB) * scale);
                P[nt][0] = e0; P[nt][1] = e1; P[nt][2] = e2; P[nt][3] = e3;
                sA += e0 + e1; sB += e2 + e3;
            }
            sA += __shfl_xor_sync(0xffffffffu, sA, 1);
            sA += __shfl_xor_sync(0xffffffffu, sA, 2);
            sB += __shfl_xor_sync(0xffffffffu, sB, 1);
            sB += __shfl_xor_sync(0xffffffffu, sB, 2);
            float iA = 1.f / sA, iB = 1.f / sB;

            const uint32_t Bv = s_ab + (head * 32) * 272 + off136 + win * 128;
            float accO[4][4] = {};
#pragma unroll
            for (int ks = 0; ks < 4; ks++) {
                uint32_t a0 = packbf(P[2 * ks][0] * iA, P[2 * ks][1] * iA);
                uint32_t a1 = packbf(P[2 * ks][2] * iB, P[2 * ks][3] * iB);
                uint32_t a2 = packbf(P[2 * ks + 1][0] * iA, P[2 * ks + 1][1] * iA);
                uint32_t a3 = packbf(P[2 * ks + 1][2] * iB, P[2 * ks + 1][3] * iB);
                uint32_t b0, b1, b2, b3;
                ldsm4(b0, b1, b2, b3, Bv + ks * 32);
                mma16816(accO[0], a0, a1, a2, a3, b0, b2);
                mma16816(accO[1], a0, a1, a2, a3, b1, b3);
                ldsm4(b0, b1, b2, b3, Bv + 4352 + ks * 32);
                mma16816(accO[2], a0, a1, a2, a3, b0, b2);
                mma16816(accO[3], a0, a1, a2, a3, b1, b3);
            }
            int ta = win * 64 + mt * 16 + g, tb = ta + 8;
#pragma unroll
            for (int nt = 0; nt < 4; nt++) {
                int cc = head * 32 + nt * 8 + q2;
                *(uint32_t*)(qs + ta * 136 + cc) = packbf(accO[nt][0], accO[nt][1]);
                *(uint32_t*)(qs + tb * 136 + cc) = packbf(accO[nt][2], accO[nt][3]);
            }
        }
        CPW(0);  // Wo staged
        __syncthreads();

        // ---- out_proj (+residual) -> y (bf16, qs) ; conv W into ks ----
        stage_w(g_wc, s_ks, tid);
        CPC();
        {
            float acc[2][4][4] = {};
            gemm128(Aqs, Wn, acc);  // o @ Wo
            __syncthreads();        // o + Wo reads done
#pragma unroll
            for (int m = 0; m < 2; m++)
#pragma unroll
                for (int nt = 0; nt < 4; nt++) {
                    int cc = nq * 32 + nt * 8 + q2;
                    int ra = mq * 32 + m * 16 + g, rb = ra + 8;
                    float y00 = acc[m][nt][0] + bias[640 + cc]     + xf[cc * 132 + ra];
                    float y01 = acc[m][nt][1] + bias[640 + cc + 1] + xf[(cc + 1) * 132 + ra];
                    float y10 = acc[m][nt][2] + bias[640 + cc]     + xf[cc * 132 + rb];
                    float y11 = acc[m][nt][3] + bias[640 + cc + 1] + xf[(cc + 1) * 132 + rb];
                    *(uint32_t*)(qs + ra * 136 + cc) = packbf(y00, y01);
                    *(uint32_t*)(qs + rb * 136 + cc) = packbf(y10, y11);
                }
        }
        CPW(0);  // conv W ready
        __syncthreads();

        // ---- conv: single GEMM y @ Wc ----
        {
            float acc[2][4][4] = {};
            gemm128(Aqs, Wk, acc);
            __syncthreads();  // all qs + Wc reads done -> outs overlay safe

            // epilogue: outs = acc + conv_b + x, into dead qs/ab (f32 [c][132])
            float* obase = (nq < 2) ? outs_lo : outs_hi;
            int csub = (nq < 2) ? 0 : 64;
#pragma unroll
            for (int m = 0; m < 2; m++)
#pragma unroll
                for (int nt = 0; nt < 4; nt++) {
                    int cc = nq * 32 + nt * 8 + q2;
                    int c0 = cc - csub;
                    int ra = mq * 32 + m * 16 + g, rb = ra + 8;
                    obase[c0 * 132 + ra]       = acc[m][nt][0] + bias[768 + cc]     + xf[cc * 132 + ra];
                    obase[(c0 + 1) * 132 + ra] = acc[m][nt][1] + bias[768 + cc + 1] + xf[(cc + 1) * 132 + ra];
                    obase[c0 * 132 + rb]       = acc[m][nt][2] + bias[768 + cc]     + xf[cc * 132 + rb];
                    obase[(c0 + 1) * 132 + rb] = acc[m][nt][3] + bias[768 + cc + 1] + xf[(cc + 1) * 132 + rb];
                }
        }
        __syncthreads();  // outs visible; xf fully read -> prefetch can land

        // ---- prefetch next window + Wq + Wk BEFORE the store ----
        const bool more = (w + GRID < NWIN);
        if (more) {
            load_x(x, w + GRID, s_xf, tid);          // group: x
            stage_w(g_win, s_w, tid);
            stage_w(g_win + 16384, s_ks, tid);
            CPC();                                   // group: Wq+Wk
        }

        // ---- store from outs (qs/ab overlays) ----
        float* ob = out + (size_t)b * 128 * 262144;
#pragma unroll
        for (int it = 0; it < 4; it++) {
            int idx = it * 512 + tid;
            int c = idx >> 5, rem = idx & 31;
            int win = rem >> 4, row = rem & 15;
            int dd = row >> 2, hh = row & 3;
            *(float4*)(ob + (size_t)c * 262144 + (size_t)(d0 + dd) * 4096 +
                       (h0 + hh) * 64 + wp + win * 4) =
                *(float4*)(outs_lo + c * 132 + win * 64 + row * 4);
        }
#pragma unroll
        for (int it = 4; it < 8; it++) {
            int idx = it * 512 + tid;
            int c = idx >> 5, rem = idx & 31;
            int win = rem >> 4, row = rem & 15;
            int dd = row >> 2, hh = row & 3;
            *(float4*)(ob + (size_t)c * 262144 + (size_t)(d0 + dd) * 4096 +
                       (h0 + hh) * 64 + wp + win * 4) =
                *(float4*)(outs_hi + (c - 64) * 132 + win * 64 + row * 4);
        }
        if (more) CPW(1);  // next x done (Wq+Wk waited after next LN)
        __syncthreads();   // outs reads done; xf ready for next LN
    }
}

extern "C" void kernel_launch(void* const* d_in, const int* in_sizes, int n_in,
                              void* d_out, int out_size) {
    const float* x      = (const float*)d_in[0];
    const float* ln_g   = (const float*)d_in[1];
    const float* ln_b   = (const float*)d_in[2];
    const float* in_w   = (const float*)d_in[3];
    const float* in_b   = (const float*)d_in[4];
    const float* out_w  = (const float*)d_in[5];
    const float* out_b  = (const float*)d_in[6];
    const float* conv_w = (const float*)d_in[7];
    const float* conv_b = (const float*)d_in[8];
    float* out = (float*)d_out;

    convert_weights_kernel<<<192, 256>>>(in_w, out_w, conv_w);

    cudaFuncSetAttribute(fused_wsa3d_kernel,
                         cudaFuncAttributeMaxDynamicSharedMemorySize, SMEM_BYTES);
    fused_wsa3d_kernel<<<GRID, 512, SMEM_BYTES>>>(x, ln_g, ln_b, in_b, out_b,
                                                  conv_b, out);
}

// round 15
// speedup vs baseline: 1.1330x; 1.1143x over previous
#include <cuda_runtime.h>
#include <cuda_bf16.h>
#include <cstdint>

// ---------------------------------------------------------------------------
// v14 = v11 (best: 565us) with the V-transpose epilogue removed:
// v stored [t][c] like q/k (packed stores); attention P@V reads it via
// ldmatrix.x4.trans (fragment pairing validated in v5/v6).
// 152 persistent CTAs, 512 threads, 2 windows per iteration.
// ---------------------------------------------------------------------------

#define SMEM_BYTES 210432

#define OFF_XF    0        // f32  [128c][132t]  x residual
#define OFF_W     67584    // bf16 [128][136]    weight stage (Wq/Wv/Wo)
#define OFF_AB    102400   // bf16 [128][136]    xn -> v[t][c] -> outs_hi
#define OFF_QS    137216   // bf16 [128][136]    q -> o -> y -> outs_lo
#define OFF_KS    172032   // bf16 [128][136]    Wk -> k -> conv weights
#define OFF_BIAS  206848   // f32 [896]

#define NWIN 4096
#define GRID 152

__device__ __align__(16) __nv_bfloat16 g_win[384 * 128];
__device__ __align__(16) __nv_bfloat16 g_wout[128 * 128];
__device__ __align__(16) __nv_bfloat16 g_wc[128 * 128];

__global__ void convert_weights_kernel(const float* __restrict__ win,
                                       const float* __restrict__ wout,
                                       const float* __restrict__ wc) {
    int i = blockIdx.x * blockDim.x + threadIdx.x;
    if (i < 384 * 128) g_win[i] = __float2bfloat16(win[i]);
    if (i < 128 * 128) {
        g_wout[i] = __float2bfloat16(wout[i]);
        g_wc[i] = __float2bfloat16(wc[i]);
    }
}

__device__ __forceinline__ void mma16816(float acc[4], uint32_t a0, uint32_t a1,
                                         uint32_t a2, uint32_t a3,
                                         uint32_t b0, uint32_t b1) {
    asm volatile(
        "mma.sync.aligned.m16n8k16.row.col.f32.bf16.bf16.f32 "
        "{%0,%1,%2,%3},{%4,%5,%6,%7},{%8,%9},{%0,%1,%2,%3};\n"
        : "+f"(acc[0]), "+f"(acc[1]), "+f"(acc[2]), "+f"(acc[3])
        : "r"(a0), "r"(a1), "r"(a2), "r"(a3), "r"(b0), "r"(b1));
}

__device__ __forceinline__ uint32_t packbf(float lo, float hi) {
    uint32_t r;
    asm("cvt.rn.bf16x2.f32 %0, %1, %2;" : "=r"(r) : "f"(hi), "f"(lo));
    return r;
}

__device__ __forceinline__ void ldsm4(uint32_t& r0, uint32_t& r1, uint32_t& r2,
                                      uint32_t& r3, uint32_t addr) {
    asm volatile("ldmatrix.sync.aligned.m8n8.x4.shared.b16 {%0,%1,%2,%3},[%4];"
                 : "=r"(r0), "=r"(r1), "=r"(r2), "=r"(r3) : "r"(addr));
}

__device__ __forceinline__ void ldsm4t(uint32_t& r0, uint32_t& r1, uint32_t& r2,
                                       uint32_t& r3, uint32_t addr) {
    asm volatile("ldmatrix.sync.aligned.m8n8.x4.trans.shared.b16 {%0,%1,%2,%3},[%4];"
                 : "=r"(r0), "=r"(r1), "=r"(r2), "=r"(r3) : "r"(addr));
}

__device__ __forceinline__ uint32_t su32(const void* p) {
    return (uint32_t)__cvta_generic_to_shared(p);
}

#define CPA16(dst, src) \
    asm volatile("cp.async.cg.shared.global [%0],[%1],16;" ::"r"(dst), "l"(src))
#define CPC() asm volatile("cp.async.commit_group;")
#define CPW(n) asm volatile("cp.async.wait_group %0;" ::"n"(n))

__device__ __forceinline__ void stage_w(const __nv_bfloat16* __restrict__ src,
                                        uint32_t dstu, int tid) {
#pragma unroll
    for (int it = 0; it < 4; it++) {
        int idx = it * 512 + tid;
        int row = idx >> 4, cq = idx & 15;
        CPA16(dstu + row * 272 + cq * 16, src + row * 128 + cq * 8);
    }
}

// issue cp.async for one window-pair of x into xf
__device__ __forceinline__ void load_x(const float* __restrict__ x, int w,
                                       uint32_t s_xf, int tid) {
    const int b = w >> 11;
    const int r = w & 2047;
    const int d0 = (r >> 7) * 4, h0 = ((r >> 3) & 15) * 4, wp = (r & 7) * 8;
    const float* xb = x + (size_t)b * 128 * 262144;
#pragma unroll
    for (int it = 0; it < 8; it++) {
        int idx = it * 512 + tid;
        int c = idx >> 5, rem = idx & 31;
        int win = rem >> 4, row = rem & 15;
        int dd = row >> 2, hh = row & 3;
        CPA16(s_xf + (c * 132 + win * 64 + row * 4) * 4,
              xb + (size_t)c * 262144 + (size_t)(d0 + dd) * 4096 +
                  (h0 + hh) * 64 + wp + win * 4);
    }
    CPC();
}

// D[32][32] += A[32 rows @Au][128] @ B[32 rows @Wu][128]^T, row stride 272B
__device__ __forceinline__ void gemm128(uint32_t Au, uint32_t Wu,
                                        float acc[2][4][4]) {
#pragma unroll
    for (int k = 0; k < 8; k++) {
        uint32_t a0, a1, a2, a3, e0, e1, e2, e3;
        uint32_t b0, b1, b2, b3, c0, c1, c2, c3;
        ldsm4(a0, a1, a2, a3, Au + k * 32);
        ldsm4(e0, e1, e2, e3, Au + 4352 + k * 32);
        ldsm4(b0, b1, b2, b3, Wu + k * 32);
        ldsm4(c0, c1, c2, c3, Wu + 4352 + k * 32);
        mma16816(acc[0][0], a0, a1, a2, a3, b0, b2);
        mma16816(acc[0][1], a0, a1, a2, a3, b1, b3);
        mma16816(acc[0][2], a0, a1, a2, a3, c0, c2);
        mma16816(acc[0][3], a0, a1, a2, a3, c1, c3);
        mma16816(acc[1][0], e0, e1, e2, e3, b0, b2);
        mma16816(acc[1][1], e0, e1, e2, e3, b1, b3);
        mma16816(acc[1][2], e0, e1, e2, e3, c0, c2);
        mma16816(acc[1][3], e0, e1, e2, e3, c1, c3);
    }
}

// dual-N GEMM: A loaded once, feeds two B matrices (Wq and Wk)
__device__ __forceinline__ void gemm128_dual(uint32_t Au, uint32_t W1,
                                             uint32_t W2, float aq[2][4][4],
                                             float ak[2][4][4]) {
#pragma unroll
    for (int k = 0; k < 8; k++) {
        uint32_t a0, a1, a2, a3, e0, e1, e2, e3;
        ldsm4(a0, a1, a2, a3, Au + k * 32);
        ldsm4(e0, e1, e2, e3, Au + 4352 + k * 32);
        {
            uint32_t b0, b1, b2, b3, c0, c1, c2, c3;
            ldsm4(b0, b1, b2, b3, W1 + k * 32);
            ldsm4(c0, c1, c2, c3, W1 + 4352 + k * 32);
            mma16816(aq[0][0], a0, a1, a2, a3, b0, b2);
            mma16816(aq[0][1], a0, a1, a2, a3, b1, b3);
            mma16816(aq[0][2], a0, a1, a2, a3, c0, c2);
            mma16816(aq[0][3], a0, a1, a2, a3, c1, c3);
            mma16816(aq[1][0], e0, e1, e2, e3, b0, b2);
            mma16816(aq[1][1], e0, e1, e2, e3, b1, b3);
            mma16816(aq[1][2], e0, e1, e2, e3, c0, c2);
            mma16816(aq[1][3], e0, e1, e2, e3, c1, c3);
        }
        {
            uint32_t b0, b1, b2, b3, c0, c1, c2, c3;
            ldsm4(b0, b1, b2, b3, W2 + k * 32);
            ldsm4(c0, c1, c2, c3, W2 + 4352 + k * 32);
            mma16816(ak[0][0], a0, a1, a2, a3, b0, b2);
            mma16816(ak[0][1], a0, a1, a2, a3, b1, b3);
            mma16816(ak[0][2], a0, a1, a2, a3, c0, c2);
            mma16816(ak[0][3], a0, a1, a2, a3, c1, c3);
            mma16816(ak[1][0], e0, e1, e2, e3, b0, b2);
            mma16816(ak[1][1], e0, e1, e2, e3, b1, b3);
            mma16816(ak[1][2], e0, e1, e2, e3, c0, c2);
            mma16816(ak[1][3], e0, e1, e2, e3, c1, c3);
        }
    }
}

__global__ void __launch_bounds__(512, 1)
fused_wsa3d_kernel(const float* __restrict__ x,
                   const float* __restrict__ ln_g, const float* __restrict__ ln_b,
                   const float* __restrict__ in_b, const float* __restrict__ out_b,
                   const float* __restrict__ conv_b,
                   float* __restrict__ out) {
    extern __shared__ char sm[];
    float* xf = (float*)(sm + OFF_XF);                      // [128c][132t]
    __nv_bfloat16* ab = (__nv_bfloat16*)(sm + OFF_AB);
    __nv_bfloat16* qs = (__nv_bfloat16*)(sm + OFF_QS);
    __nv_bfloat16* ks_ = (__nv_bfloat16*)(sm + OFF_KS);
    float* bias = (float*)(sm + OFF_BIAS);
    float* outs_lo = (float*)(sm + OFF_QS);   // c 0..63   [64][132]
    float* outs_hi = (float*)(sm + OFF_AB);   // c 64..127 [64][132]

    const int tid = threadIdx.x;
    const int warp = tid >> 5, lane = tid & 31;
    const int g = lane >> 2, q2 = (lane & 3) * 2;
    const int lane16 = lane & 15, laneh = lane >> 4;
    const int mq = warp & 3, nq = warp >> 2;

    const uint32_t s_xf = su32(xf);
    const uint32_t s_ab = su32(ab);
    const uint32_t s_qs = su32(qs);
    const uint32_t s_ks = su32(ks_);
    const uint32_t s_w = su32(sm + OFF_W);
    const uint32_t off136 = (uint32_t)(lane16 * 272 + laneh * 16);

    const uint32_t Aab = s_ab + mq * 32 * 272 + off136;
    const uint32_t Aqs = s_qs + mq * 32 * 272 + off136;
    const uint32_t Wn = s_w + nq * 32 * 272 + off136;
    const uint32_t Wk = s_ks + nq * 32 * 272 + off136;

    // ---- biases once ----
    for (int i = tid; i < 896; i += 512) {
        float v;
        if (i < 128)      v = ln_g[i];
        else if (i < 256) v = ln_b[i - 128];
        else if (i < 640) v = in_b[i - 256];
        else if (i < 768) v = out_b[i - 640];
        else              v = conv_b[i - 768];
        bias[i] = v;
    }

    // ---- first x window + Wq(->W) + Wk(->ks) ----
    load_x(x, blockIdx.x, s_xf, tid);            // group: x
    stage_w(g_win, s_w, tid);
    stage_w(g_win + 16384, s_ks, tid);
    CPC();                                       // group: Wq+Wk
    CPW(1);                                      // x done
    __syncthreads();

    for (int w = blockIdx.x; w < NWIN; w += GRID) {
        const int b = w >> 11;
        const int r = w & 2047;
        const int d0 = (r >> 7) * 4, h0 = ((r >> 3) & 15) * 4, wp = (r & 7) * 8;

        // ---- LayerNorm (4 threads / token) ----
        {
            int t = tid >> 2, j = tid & 3;
            float s = 0.f, s2 = 0.f;
#pragma unroll
            for (int i = 0; i < 32; i++) {
                float v = xf[(j + 4 * i) * 132 + t];
                s += v; s2 += v * v;
            }
            s  += __shfl_xor_sync(0xffffffffu, s, 1);
            s  += __shfl_xor_sync(0xffffffffu, s, 2);
            s2 += __shfl_xor_sync(0xffffffffu, s2, 1);
            s2 += __shfl_xor_sync(0xffffffffu, s2, 2);
            float mu = s * (1.f / 128.f);
            float var = s2 * (1.f / 128.f) - mu * mu;
            float rstd = rsqrtf(var + 1e-5f);
#pragma unroll
            for (int i = 0; i < 32; i++) {
                int c = j + 4 * i;
                float v = (xf[c * 132 + t] - mu) * rstd * bias[c] + bias[128 + c];
                ab[t * 136 + c] = __float2bfloat16(v);
            }
        }
        CPW(0);          // Wq + Wk staged
        __syncthreads();

        // ---- Q,K = xn @ {Wq,Wk} (dual) ; Wv staged under epilogue ----
        {
            float aq[2][4][4] = {}, ak[2][4][4] = {};
            gemm128_dual(Aab, Wn, Wk, aq, ak);
            __syncthreads();                    // Wq + Wk reads done
            stage_w(g_win + 32768, s_w, tid);   // issue Wv
            CPC();
#pragma unroll
            for (int m = 0; m < 2; m++)
#pragma unroll
                for (int nt = 0; nt < 4; nt++) {
                    int cc = nq * 32 + nt * 8 + q2;
                    int ra = mq * 32 + m * 16 + g, rb = ra + 8;
                    float bq0 = bias[256 + cc], bq1 = bias[256 + cc + 1];
                    float bk0 = bias[384 + cc], bk1 = bias[384 + cc + 1];
                    *(uint32_t*)(qs + ra * 136 + cc) = packbf(aq[m][nt][0] + bq0, aq[m][nt][1] + bq1);
                    *(uint32_t*)(qs + rb * 136 + cc) = packbf(aq[m][nt][2] + bq0, aq[m][nt][3] + bq1);
                    *(uint32_t*)(ks_ + ra * 136 + cc) = packbf(ak[m][nt][0] + bk0, ak[m][nt][1] + bk1);
                    *(uint32_t*)(ks_ + rb * 136 + cc) = packbf(ak[m][nt][2] + bk0, ak[m][nt][3] + bk1);
                }
        }
        CPW(0);
        __syncthreads();

        // ---- V = xn @ Wv -> v[t][c] into ab (packed, like q/k) ----
        {
            float acc[2][4][4] = {};
            gemm128(Aab, Wn, acc);
            __syncthreads();               // Wv reads + all xn reads done
            stage_w(g_wout, s_w, tid);
            CPC();
#pragma unroll
            for (int m = 0; m < 2; m++)
#pragma unroll
                for (int nt = 0; nt < 4; nt++) {
                    int cc = nq * 32 + nt * 8 + q2;
                    int ra = mq * 32 + m * 16 + g, rb = ra + 8;
                    float b0 = bias[512 + cc], b1 = bias[512 + cc + 1];
                    *(uint32_t*)(ab + ra * 136 + cc) = packbf(acc[m][nt][0] + b0, acc[m][nt][1] + b1);
                    *(uint32_t*)(ab + rb * 136 + cc) = packbf(acc[m][nt][2] + b0, acc[m][nt][3] + b1);
                }
        }
        __syncthreads();  // v visible (Wo in flight)

        // ---- Attention: 32 tasks (win,head,mtile), 2 per warp ----
#pragma unroll 1
        for (int ti = 0; ti < 2; ti++) {
            const int task = warp + ti * 16;
            const int win = task >> 4;
            const int head = (task >> 2) & 3;
            const int mt = task & 3;
            const uint32_t Aq = s_qs + (win * 64 + mt * 16) * 272 + off136 + head * 64;
            const uint32_t Bk = s_ks + (win * 64) * 272 + off136 + head * 64;

            float P[8][4] = {};
#pragma unroll
            for (int k2 = 0; k2 < 2; k2++) {
                uint32_t a0, a1, a2, a3;
                ldsm4(a0, a1, a2, a3, Aq + k2 * 32);
#pragma unroll
                for (int p = 0; p < 4; p++) {
                    uint32_t b0, b1, b2, b3;
                    ldsm4(b0, b1, b2, b3, Bk + p * 4352 + k2 * 32);
                    mma16816(P[2 * p], a0, a1, a2, a3, b0, b2);
                    mma16816(P[2 * p + 1], a0, a1, a2, a3, b1, b3);
                }
            }
            const float scale = 0.17677669529663687f;  // 1/sqrt(32)
            float mA = -1e30f, mB = -1e30f;
#pragma unroll
            for (int nt = 0; nt < 8; nt++) {
                mA = fmaxf(mA, fmaxf(P[nt][0], P[nt][1]));
                mB = fmaxf(mB, fmaxf(P[nt][2], P[nt][3]));
            }
            mA = fmaxf(mA, __shfl_xor_sync(0xffffffffu, mA, 1));
            mA = fmaxf(mA, __shfl_xor_sync(0xffffffffu, mA, 2));
            mB = fmaxf(mB, __shfl_xor_sync(0xffffffffu, mB, 1));
            mB = fmaxf(mB, __shfl_xor_sync(0xffffffffu, mB, 2));
            float sA = 0.f, sB = 0.f;
#pragma unroll
            for (int nt = 0; nt < 8; nt++) {
                float e0 = __expf((P[nt][0] - mA) * scale);
                float e1 = __expf((P[nt][1] - mA) * scale);
                float e2 = __expf((P[nt][2] - mB) * scale);
                float e3 = __expf((P[nt][3] - mB) * scale);
                P[nt][0] = e0; P[nt][1] = e1; P[nt][2] = e2; P[nt][3] = e3;
                sA += e0 + e1; sB += e2 + e3;
            }
            sA += __shfl_xor_sync(0xffffffffu, sA, 1);
            sA += __shfl_xor_sync(0xffffffffu, sA, 2);
            sB += __shfl_xor_sync(0xffffffffu, sB, 1);
            sB += __shfl_xor_sync(0xffffffffu, sB, 2);
            float iA = 1.f / sA, iB = 1.f / sB;

            // V[t][c] consumed via trans-ldsm (B-frags for P@V)
            const uint32_t Bv = s_ab + (win * 64) * 272 + off136 + head * 64;
            float accO[4][4] = {};
#pragma unroll
            for (int ks = 0; ks < 4; ks++) {
                uint32_t a0 = packbf(P[2 * ks][0] * iA, P[2 * ks][1] * iA);
                uint32_t a1 = packbf(P[2 * ks][2] * iB, P[2 * ks][3] * iB);
                uint32_t a2 = packbf(P[2 * ks + 1][0] * iA, P[2 * ks + 1][1] * iA);
                uint32_t a3 = packbf(P[2 * ks + 1][2] * iB, P[2 * ks + 1][3] * iB);
                uint32_t r0, r1, r2, r3;
                ldsm4t(r0, r1, r2, r3, Bv + ks * 16 * 272);
                mma16816(accO[0], a0, a1, a2, a3, r0, r1);
                mma16816(accO[1], a0, a1, a2, a3, r2, r3);
                ldsm4t(r0, r1, r2, r3, Bv + ks * 16 * 272 + 32);
                mma16816(accO[2], a0, a1, a2, a3, r0, r1);
                mma16816(accO[3], a0, a1, a2, a3, r2, r3);
            }
            int ta = win * 64 + mt * 16 + g, tb = ta + 8;
#pragma unroll
            for (int nt = 0; nt < 4; nt++) {
                int cc = head * 32 + nt * 8 + q2;
                *(uint32_t*)(qs + ta * 136 + cc) = packbf(accO[nt][0], accO[nt][1]);
                *(uint32_t*)(qs + tb * 136 + cc) = packbf(accO[nt][2], accO[nt][3]);
            }
        }
        CPW(0);  // Wo staged
        __syncthreads();

        // ---- out_proj (+residual) -> y (bf16, qs) ; conv W into ks ----
        stage_w(g_wc, s_ks, tid);
        CPC();
        {
            float acc[2][4][4] = {};
            gemm128(Aqs, Wn, acc);  // o @ Wo
            __syncthreads();        // o + Wo reads done
#pragma unroll
            for (int m = 0; m < 2; m++)
#pragma unroll
                for (int nt = 0; nt < 4; nt++) {
                    int cc = nq * 32 + nt * 8 + q2;
                    int ra = mq * 32 + m * 16 + g, rb = ra + 8;
                    float y00 = acc[m][nt][0] + bias[640 + cc]     + xf[cc * 132 + ra];
                    float y01 = acc[m][nt][1] + bias[640 + cc + 1] + xf[(cc + 1) * 132 + ra];
                    float y10 = acc[m][nt][2] + bias[640 + cc]     + xf[cc * 132 + rb];
                    float y11 = acc[m][nt][3] + bias[640 + cc + 1] + xf[(cc + 1) * 132 + rb];
                    *(uint32_t*)(qs + ra * 136 + cc) = packbf(y00, y01);
                    *(uint32_t*)(qs + rb * 136 + cc) = packbf(y10, y11);
                }
        }
        CPW(0);  // conv W ready
        __syncthreads();

        // ---- conv: single GEMM y @ Wc ----
        {
            float acc[2][4][4] = {};
            gemm128(Aqs, Wk, acc);
            __syncthreads();  // all qs + Wc reads done -> outs overlay safe

            // epilogue: outs = acc + conv_b + x, into dead qs/ab (f32 [c][132])
            float* obase = (nq < 2) ? outs_lo : outs_hi;
            int csub = (nq < 2) ? 0 : 64;
#pragma unroll
            for (int m = 0; m < 2; m++)
#pragma unroll
                for (int nt = 0; nt < 4; nt++) {
                    int cc = nq * 32 + nt * 8 + q2;
                    int c0 = cc - csub;
                    int ra = mq * 32 + m * 16 + g, rb = ra + 8;
                    obase[c0 * 132 + ra]       = acc[m][nt][0] + bias[768 + cc]     + xf[cc * 132 + ra];
                    obase[(c0 + 1) * 132 + ra] = acc[m][nt][1] + bias[768 + cc + 1] + xf[(cc + 1) * 132 + ra];
                    obase[c0 * 132 + rb]       = acc[m][nt][2] + bias[768 + cc]     + xf[cc * 132 + rb];
                    obase[(c0 + 1) * 132 + rb] = acc[m][nt][3] + bias[768 + cc + 1] + xf[(cc + 1) * 132 + rb];
                }
        }
        __syncthreads();  // outs visible; xf fully read -> prefetch can land

        // ---- prefetch next window + Wq + Wk BEFORE the store ----
        const bool more = (w + GRID < NWIN);
        if (more) {
            load_x(x, w + GRID, s_xf, tid);          // group: x
            stage_w(g_win, s_w, tid);
            stage_w(g_win + 16384, s_ks, tid);
            CPC();                                   // group: Wq+Wk
        }

        // ---- store from outs (qs/ab overlays) ----
        float* ob = out + (size_t)b * 128 * 262144;
#pragma unroll
        for (int it = 0; it < 4; it++) {
            int idx = it * 512 + tid;
            int c = idx >> 5, rem = idx & 31;
            int win = rem >> 4, row = rem & 15;
            int dd = row >> 2, hh = row & 3;
            *(float4*)(ob + (size_t)c * 262144 + (size_t)(d0 + dd) * 4096 +
                       (h0 + hh) * 64 + wp + win * 4) =
                *(float4*)(outs_lo + c * 132 + win * 64 + row * 4);
        }
#pragma unroll
        for (int it = 4; it < 8; it++) {
            int idx = it * 512 + tid;
            int c = idx >> 5, rem = idx & 31;
            int win = rem >> 4, row = rem & 15;
            int dd = row >> 2, hh = row & 3;
            *(float4*)(ob + (size_t)c * 262144 + (size_t)(d0 + dd) * 4096 +
                       (h0 + hh) * 64 + wp + win * 4) =
                *(float4*)(outs_hi + (c - 64) * 132 + win * 64 + row * 4);
        }
        if (more) CPW(1);  // next x done (Wq+Wk waited after next LN)
        __syncthreads();   // outs reads done; xf ready for next LN
    }
}

extern "C" void kernel_launch(void* const* d_in, const int* in_sizes, int n_in,
                              void* d_out, int out_size) {
    const float* x      = (const float*)d_in[0];
    const float* ln_g   = (const float*)d_in[1];
    const float* ln_b   = (const float*)d_in[2];
    const float* in_w   = (const float*)d_in[3];
    const float* in_b   = (const float*)d_in[4];
    const float* out_w  = (const float*)d_in[5];
    const float* out_b  = (const float*)d_in[6];
    const float* conv_w = (const float*)d_in[7];
    const float* conv_b = (const float*)d_in[8];
    float* out = (float*)d_out;

    convert_weights_kernel<<<192, 256>>>(in_w, out_w, conv_w);

    cudaFuncSetAttribute(fused_wsa3d_kernel,
                         cudaFuncAttributeMaxDynamicSharedMemorySize, SMEM_BYTES);
    fused_wsa3d_kernel<<<GRID, 512, SMEM_BYTES>>>(x, ln_g, ln_b, in_b, out_b,
                                                  conv_b, out);
}

// round 16
// speedup vs baseline: 1.1502x; 1.0152x over previous
#include <cuda_runtime.h>
#include <cuda_bf16.h>
#include <cstdint>

// ---------------------------------------------------------------------------
// v15 = v14 (best: 559us) + scalar-pipe shavings:
//   - LN reads xf once into registers (vv[32], LN-scoped; original j+4i map)
//   - softmax: exp2f(fma(P,C,-m*C)) with C=scale*log2e (1 FMA + 1 MUFU/elem)
// 152 persistent CTAs, 512 threads, 2 windows per iteration.
// ---------------------------------------------------------------------------

#define SMEM_BYTES 210432

#define OFF_XF    0        // f32  [128c][132t]  x residual
#define OFF_W     67584    // bf16 [128][136]    weight stage (Wq/Wv/Wo)
#define OFF_AB    102400   // bf16 [128][136]    xn -> v[t][c] -> outs_hi
#define OFF_QS    137216   // bf16 [128][136]    q -> o -> y -> outs_lo
#define OFF_KS    172032   // bf16 [128][136]    Wk -> k -> conv weights
#define OFF_BIAS  206848   // f32 [896]

#define NWIN 4096
#define GRID 152

__device__ __align__(16) __nv_bfloat16 g_win[384 * 128];
__device__ __align__(16) __nv_bfloat16 g_wout[128 * 128];
__device__ __align__(16) __nv_bfloat16 g_wc[128 * 128];

__global__ void convert_weights_kernel(const float* __restrict__ win,
                                       const float* __restrict__ wout,
                                       const float* __restrict__ wc) {
    int i = blockIdx.x * blockDim.x + threadIdx.x;
    if (i < 384 * 128) g_win[i] = __float2bfloat16(win[i]);
    if (i < 128 * 128) {
        g_wout[i] = __float2bfloat16(wout[i]);
        g_wc[i] = __float2bfloat16(wc[i]);
    }
}

__device__ __forceinline__ void mma16816(float acc[4], uint32_t a0, uint32_t a1,
                                         uint32_t a2, uint32_t a3,
                                         uint32_t b0, uint32_t b1) {
    asm volatile(
        "mma.sync.aligned.m16n8k16.row.col.f32.bf16.bf16.f32 "
        "{%0,%1,%2,%3},{%4,%5,%6,%7},{%8,%9},{%0,%1,%2,%3};\n"
        : "+f"(acc[0]), "+f"(acc[1]), "+f"(acc[2]), "+f"(acc[3])
        : "r"(a0), "r"(a1), "r"(a2), "r"(a3), "r"(b0), "r"(b1));
}

__device__ __forceinline__ uint32_t packbf(float lo, float hi) {
    uint32_t r;
    asm("cvt.rn.bf16x2.f32 %0, %1, %2;" : "=r"(r) : "f"(hi), "f"(lo));
    return r;
}

__device__ __forceinline__ void ldsm4(uint32_t& r0, uint32_t& r1, uint32_t& r2,
                                      uint32_t& r3, uint32_t addr) {
    asm volatile("ldmatrix.sync.aligned.m8n8.x4.shared.b16 {%0,%1,%2,%3},[%4];"
                 : "=r"(r0), "=r"(r1), "=r"(r2), "=r"(r3) : "r"(addr));
}

__device__ __forceinline__ void ldsm4t(uint32_t& r0, uint32_t& r1, uint32_t& r2,
                                       uint32_t& r3, uint32_t addr) {
    asm volatile("ldmatrix.sync.aligned.m8n8.x4.trans.shared.b16 {%0,%1,%2,%3},[%4];"
                 : "=r"(r0), "=r"(r1), "=r"(r2), "=r"(r3) : "r"(addr));
}

__device__ __forceinline__ uint32_t su32(const void* p) {
    return (uint32_t)__cvta_generic_to_shared(p);
}

#define CPA16(dst, src) \
    asm volatile("cp.async.cg.shared.global [%0],[%1],16;" ::"r"(dst), "l"(src))
#define CPC() asm volatile("cp.async.commit_group;")
#define CPW(n) asm volatile("cp.async.wait_group %0;" ::"n"(n))

__device__ __forceinline__ void stage_w(const __nv_bfloat16* __restrict__ src,
                                        uint32_t dstu, int tid) {
#pragma unroll
    for (int it = 0; it < 4; it++) {
        int idx = it * 512 + tid;
        int row = idx >> 4, cq = idx & 15;
        CPA16(dstu + row * 272 + cq * 16, src + row * 128 + cq * 8);
    }
}

// issue cp.async for one window-pair of x into xf
__device__ __forceinline__ void load_x(const float* __restrict__ x, int w,
                                       uint32_t s_xf, int tid) {
    const int b = w >> 11;
    const int r = w & 2047;
    const int d0 = (r >> 7) * 4, h0 = ((r >> 3) & 15) * 4, wp = (r & 7) * 8;
    const float* xb = x + (size_t)b * 128 * 262144;
#pragma unroll
    for (int it = 0; it < 8; it++) {
        int idx = it * 512 + tid;
        int c = idx >> 5, rem = idx & 31;
        int win = rem >> 4, row = rem & 15;
        int dd = row >> 2, hh = row & 3;
        CPA16(s_xf + (c * 132 + win * 64 + row * 4) * 4,
              xb + (size_t)c * 262144 + (size_t)(d0 + dd) * 4096 +
                  (h0 + hh) * 64 + wp + win * 4);
    }
    CPC();
}

// D[32][32] += A[32 rows @Au][128] @ B[32 rows @Wu][128]^T, row stride 272B
__device__ __forceinline__ void gemm128(uint32_t Au, uint32_t Wu,
                                        float acc[2][4][4]) {
#pragma unroll
    for (int k = 0; k < 8; k++) {
        uint32_t a0, a1, a2, a3, e0, e1, e2, e3;
        uint32_t b0, b1, b2, b3, c0, c1, c2, c3;
        ldsm4(a0, a1, a2, a3, Au + k * 32);
        ldsm4(e0, e1, e2, e3, Au + 4352 + k * 32);
        ldsm4(b0, b1, b2, b3, Wu + k * 32);
        ldsm4(c0, c1, c2, c3, Wu + 4352 + k * 32);
        mma16816(acc[0][0], a0, a1, a2, a3, b0, b2);
        mma16816(acc[0][1], a0, a1, a2, a3, b1, b3);
        mma16816(acc[0][2], a0, a1, a2, a3, c0, c2);
        mma16816(acc[0][3], a0, a1, a2, a3, c1, c3);
        mma16816(acc[1][0], e0, e1, e2, e3, b0, b2);
        mma16816(acc[1][1], e0, e1, e2, e3, b1, b3);
        mma16816(acc[1][2], e0, e1, e2, e3, c0, c2);
        mma16816(acc[1][3], e0, e1, e2, e3, c1, c3);
    }
}

// dual-N GEMM: A loaded once, feeds two B matrices (Wq and Wk)
__device__ __forceinline__ void gemm128_dual(uint32_t Au, uint32_t W1,
                                             uint32_t W2, float aq[2][4][4],
                                             float ak[2][4][4]) {
#pragma unroll
    for (int k = 0; k < 8; k++) {
        uint32_t a0, a1, a2, a3, e0, e1, e2, e3;
        ldsm4(a0, a1, a2, a3, Au + k * 32);
        ldsm4(e0, e1, e2, e3, Au + 4352 + k * 32);
        {
            uint32_t b0, b1, b2, b3, c0, c1, c2, c3;
            ldsm4(b0, b1, b2, b3, W1 + k * 32);
            ldsm4(c0, c1, c2, c3, W1 + 4352 + k * 32);
            mma16816(aq[0][0], a0, a1, a2, a3, b0, b2);
            mma16816(aq[0][1], a0, a1, a2, a3, b1, b3);
            mma16816(aq[0][2], a0, a1, a2, a3, c0, c2);
            mma16816(aq[0][3], a0, a1, a2, a3, c1, c3);
            mma16816(aq[1][0], e0, e1, e2, e3, b0, b2);
            mma16816(aq[1][1], e0, e1, e2, e3, b1, b3);
            mma16816(aq[1][2], e0, e1, e2, e3, c0, c2);
            mma16816(aq[1][3], e0, e1, e2, e3, c1, c3);
        }
        {
            uint32_t b0, b1, b2, b3, c0, c1, c2, c3;
            ldsm4(b0, b1, b2, b3, W2 + k * 32);
            ldsm4(c0, c1, c2, c3, W2 + 4352 + k * 32);
            mma16816(ak[0][0], a0, a1, a2, a3, b0, b2);
            mma16816(ak[0][1], a0, a1, a2, a3, b1, b3);
            mma16816(ak[0][2], a0, a1, a2, a3, c0, c2);
            mma16816(ak[0][3], a0, a1, a2, a3, c1, c3);
            mma16816(ak[1][0], e0, e1, e2, e3, b0, b2);
            mma16816(ak[1][1], e0, e1, e2, e3, b1, b3);
            mma16816(ak[1][2], e0, e1, e2, e3, c0, c2);
            mma16816(ak[1][3], e0, e1, e2, e3, c1, c3);
        }
    }
}

__global__ void __launch_bounds__(512, 1)
fused_wsa3d_kernel(const float* __restrict__ x,
                   const float* __restrict__ ln_g, const float* __restrict__ ln_b,
                   const float* __restrict__ in_b, const float* __restrict__ out_b,
                   const float* __restrict__ conv_b,
                   float* __restrict__ out) {
    extern __shared__ char sm[];
    float* xf = (float*)(sm + OFF_XF);                      // [128c][132t]
    __nv_bfloat16* ab = (__nv_bfloat16*)(sm + OFF_AB);
    __nv_bfloat16* qs = (__nv_bfloat16*)(sm + OFF_QS);
    __nv_bfloat16* ks_ = (__nv_bfloat16*)(sm + OFF_KS);
    float* bias = (float*)(sm + OFF_BIAS);
    float* outs_lo = (float*)(sm + OFF_QS);   // c 0..63   [64][132]
    float* outs_hi = (float*)(sm + OFF_AB);   // c 64..127 [64][132]

    const int tid = threadIdx.x;
    const int warp = tid >> 5, lane = tid & 31;
    const int g = lane >> 2, q2 = (lane & 3) * 2;
    const int lane16 = lane & 15, laneh = lane >> 4;
    const int mq = warp & 3, nq = warp >> 2;

    const uint32_t s_xf = su32(xf);
    const uint32_t s_ab = su32(ab);
    const uint32_t s_qs = su32(qs);
    const uint32_t s_ks = su32(ks_);
    const uint32_t s_w = su32(sm + OFF_W);
    const uint32_t off136 = (uint32_t)(lane16 * 272 + laneh * 16);

    const uint32_t Aab = s_ab + mq * 32 * 272 + off136;
    const uint32_t Aqs = s_qs + mq * 32 * 272 + off136;
    const uint32_t Wn = s_w + nq * 32 * 272 + off136;
    const uint32_t Wk = s_ks + nq * 32 * 272 + off136;

    // ---- biases once ----
    for (int i = tid; i < 896; i += 512) {
        float v;
        if (i < 128)      v = ln_g[i];
        else if (i < 256) v = ln_b[i - 128];
        else if (i < 640) v = in_b[i - 256];
        else if (i < 768) v = out_b[i - 640];
        else              v = conv_b[i - 768];
        bias[i] = v;
    }

    // ---- first x window + Wq(->W) + Wk(->ks) ----
    load_x(x, blockIdx.x, s_xf, tid);            // group: x
    stage_w(g_win, s_w, tid);
    stage_w(g_win + 16384, s_ks, tid);
    CPC();                                       // group: Wq+Wk
    CPW(1);                                      // x done
    __syncthreads();

    for (int w = blockIdx.x; w < NWIN; w += GRID) {
        const int b = w >> 11;
        const int r = w & 2047;
        const int d0 = (r >> 7) * 4, h0 = ((r >> 3) & 15) * 4, wp = (r & 7) * 8;

        // ---- LayerNorm (4 threads / token; xf read once) ----
        {
            int t = tid >> 2, j = tid & 3;
            float vv[32];
            float s = 0.f, s2 = 0.f;
#pragma unroll
            for (int i = 0; i < 32; i++) {
                vv[i] = xf[(j + 4 * i) * 132 + t];
                s += vv[i]; s2 += vv[i] * vv[i];
            }
            s  += __shfl_xor_sync(0xffffffffu, s, 1);
            s  += __shfl_xor_sync(0xffffffffu, s, 2);
            s2 += __shfl_xor_sync(0xffffffffu, s2, 1);
            s2 += __shfl_xor_sync(0xffffffffu, s2, 2);
            float mu = s * (1.f / 128.f);
            float var = s2 * (1.f / 128.f) - mu * mu;
            float rstd = rsqrtf(var + 1e-5f);
#pragma unroll
            for (int i = 0; i < 32; i++) {
                int c = j + 4 * i;
                float v = (vv[i] - mu) * rstd * bias[c] + bias[128 + c];
                ab[t * 136 + c] = __float2bfloat16(v);
            }
        }
        CPW(0);          // Wq + Wk staged
        __syncthreads();

        // ---- Q,K = xn @ {Wq,Wk} (dual) ; Wv staged under epilogue ----
        {
            float aq[2][4][4] = {}, ak[2][4][4] = {};
            gemm128_dual(Aab, Wn, Wk, aq, ak);
            __syncthreads();                    // Wq + Wk reads done
            stage_w(g_win + 32768, s_w, tid);   // issue Wv
            CPC();
#pragma unroll
            for (int m = 0; m < 2; m++)
#pragma unroll
                for (int nt = 0; nt < 4; nt++) {
                    int cc = nq * 32 + nt * 8 + q2;
                    int ra = mq * 32 + m * 16 + g, rb = ra + 8;
                    float bq0 = bias[256 + cc], bq1 = bias[256 + cc + 1];
                    float bk0 = bias[384 + cc], bk1 = bias[384 + cc + 1];
                    *(uint32_t*)(qs + ra * 136 + cc) = packbf(aq[m][nt][0] + bq0, aq[m][nt][1] + bq1);
                    *(uint32_t*)(qs + rb * 136 + cc) = packbf(aq[m][nt][2] + bq0, aq[m][nt][3] + bq1);
                    *(uint32_t*)(ks_ + ra * 136 + cc) = packbf(ak[m][nt][0] + bk0, ak[m][nt][1] + bk1);
                    *(uint32_t*)(ks_ + rb * 136 + cc) = packbf(ak[m][nt][2] + bk0, ak[m][nt][3] + bk1);
                }
        }
        CPW(0);
        __syncthreads();

        // ---- V = xn @ Wv -> v[t][c] into ab (packed, like q/k) ----
        {
            float acc[2][4][4] = {};
            gemm128(Aab, Wn, acc);
            __syncthreads();               // Wv reads + all xn reads done
            stage_w(g_wout, s_w, tid);
            CPC();
#pragma unroll
            for (int m = 0; m < 2; m++)
#pragma unroll
                for (int nt = 0; nt < 4; nt++) {
                    int cc = nq * 32 + nt * 8 + q2;
                    int ra = mq * 32 + m * 16 + g, rb = ra + 8;
                    float b0 = bias[512 + cc], b1 = bias[512 + cc + 1];
                    *(uint32_t*)(ab + ra * 136 + cc) = packbf(acc[m][nt][0] + b0, acc[m][nt][1] + b1);
                    *(uint32_t*)(ab + rb * 136 + cc) = packbf(acc[m][nt][2] + b0, acc[m][nt][3] + b1);
                }
        }
        __syncthreads();  // v visible (Wo in flight)

        // ---- Attention: 32 tasks (win,head,mtile), 2 per warp ----
#pragma unroll 1
        for (int ti = 0; ti < 2; ti++) {
            const int task = warp + ti * 16;
            const int win = task >> 4;
            const int head = (task >> 2) & 3;
            const int mt = task & 3;
            const uint32_t Aq = s_qs + (win * 64 + mt * 16) * 272 + off136 + head * 64;
            const uint32_t Bk = s_ks + (win * 64) * 272 + off136 + head * 64;

            float P[8][4] = {};
#pragma unroll
            for (int k2 = 0; k2 < 2; k2++) {
                uint32_t a0, a1, a2, a3;
                ldsm4(a0, a1, a2, a3, Aq + k2 * 32);
#pragma unroll
                for (int p = 0; p < 4; p++) {
                    uint32_t b0, b1, b2, b3;
                    ldsm4(b0, b1, b2, b3, Bk + p * 4352 + k2 * 32);
                    mma16816(P[2 * p], a0, a1, a2, a3, b0, b2);
                    mma16816(P[2 * p + 1], a0, a1, a2, a3, b1, b3);
                }
            }
            // C = (1/sqrt(32)) * log2(e)
            const float C = 0.17677669529663687f * 1.4426950408889634f;
            float mA = -1e30f, mB = -1e30f;
#pragma unroll
            for (int nt = 0; nt < 8; nt++) {
                mA = fmaxf(mA, fmaxf(P[nt][0], P[nt][1]));
                mB = fmaxf(mB, fmaxf(P[nt][2], P[nt][3]));
            }
            mA = fmaxf(mA, __shfl_xor_sync(0xffffffffu, mA, 1));
            mA = fmaxf(mA, __shfl_xor_sync(0xffffffffu, mA, 2));
            mB = fmaxf(mB, __shfl_xor_sync(0xffffffffu, mB, 1));
            mB = fmaxf(mB, __shfl_xor_sync(0xffffffffu, mB, 2));
            float mAC = mA * C, mBC = mB * C;
            float sA = 0.f, sB = 0.f;
#pragma unroll
            for (int nt = 0; nt < 8; nt++) {
                float e0 = exp2f(fmaf(P[nt][0], C, -mAC));
                float e1 = exp2f(fmaf(P[nt][1], C, -mAC));
                float e2 = exp2f(fmaf(P[nt][2], C, -mBC));
                float e3 = exp2f(fmaf(P[nt][3], C, -mBC));
                P[nt][0] = e0; P[nt][1] = e1; P[nt][2] = e2; P[nt][3] = e3;
                sA += e0 + e1; sB += e2 + e3;
            }
            sA += __shfl_xor_sync(0xffffffffu, sA, 1);
            sA += __shfl_xor_sync(0xffffffffu, sA, 2);
            sB += __shfl_xor_sync(0xffffffffu, sB, 1);
            sB += __shfl_xor_sync(0xffffffffu, sB, 2);
            float iA = 1.f / sA, iB = 1.f / sB;

            // V[t][c] consumed via trans-ldsm (B-frags for P@V)
            const uint32_t Bv = s_ab + (win * 64) * 272 + off136 + head * 64;
            float accO[4][4] = {};
#pragma unroll
            for (int ks = 0; ks < 4; ks++) {
                uint32_t a0 = packbf(P[2 * ks][0] * iA, P[2 * ks][1] * iA);
                uint32_t a1 = packbf(P[2 * ks][2] * iB, P[2 * ks][3] * iB);
                uint32_t a2 = packbf(P[2 * ks + 1][0] * iA, P[2 * ks + 1][1] * iA);
                uint32_t a3 = packbf(P[2 * ks + 1][2] * iB, P[2 * ks + 1][3] * iB);
                uint32_t r0, r1, r2, r3;
                ldsm4t(r0, r1, r2, r3, Bv + ks * 16 * 272);
                mma16816(accO[0], a0, a1, a2, a3, r0, r1);
                mma16816(accO[1], a0, a1, a2, a3, r2, r3);
                ldsm4t(r0, r1, r2, r3, Bv + ks * 16 * 272 + 32);
                mma16816(accO[2], a0, a1, a2, a3, r0, r1);
                mma16816(accO[3], a0, a1, a2, a3, r2, r3);
            }
            int ta = win * 64 + mt * 16 + g, tb = ta + 8;
#pragma unroll
            for (int nt = 0; nt < 4; nt++) {
                int cc = head * 32 + nt * 8 + q2;
                *(uint32_t*)(qs + ta * 136 + cc) = packbf(accO[nt][0], accO[nt][1]);
                *(uint32_t*)(qs + tb * 136 + cc) = packbf(accO[nt][2], accO[nt][3]);
            }
        }
        CPW(0);  // Wo staged
        __syncthreads();

        // ---- out_proj (+residual) -> y (bf16, qs) ; conv W into ks ----
        stage_w(g_wc, s_ks, tid);
        CPC();
        {
            float acc[2][4][4] = {};
            gemm128(Aqs, Wn, acc);  // o @ Wo
            __syncthreads();        // o + Wo reads done
#pragma unroll
            for (int m = 0; m < 2; m++)
#pragma unroll
                for (int nt = 0; nt < 4; nt++) {
                    int cc = nq * 32 + nt * 8 + q2;
                    int ra = mq * 32 + m * 16 + g, rb = ra + 8;
                    float y00 = acc[m][nt][0] + bias[640 + cc]     + xf[cc * 132 + ra];
                    float y01 = acc[m][nt][1] + bias[640 + cc + 1] + xf[(cc + 1) * 132 + ra];
                    float y10 = acc[m][nt][2] + bias[640 + cc]     + xf[cc * 132 + rb];
                    float y11 = acc[m][nt][3] + bias[640 + cc + 1] + xf[(cc + 1) * 132 + rb];
                    *(uint32_t*)(qs + ra * 136 + cc) = packbf(y00, y01);
                    *(uint32_t*)(qs + rb * 136 + cc) = packbf(y10, y11);
                }
        }
        CPW(0);  // conv W ready
        __syncthreads();

        // ---- conv: single GEMM y @ Wc ----
        {
            float acc[2][4][4] = {};
            gemm128(Aqs, Wk, acc);
            __syncthreads();  // all qs + Wc reads done -> outs overlay safe

            // epilogue: outs = acc + conv_b + x, into dead qs/ab (f32 [c][132])
            float* obase = (nq < 2) ? outs_lo : outs_hi;
            int csub = (nq < 2) ? 0 : 64;
#pragma unroll
            for (int m = 0; m < 2; m++)
#pragma unroll
                for (int nt = 0; nt < 4; nt++) {
                    int cc = nq * 32 + nt * 8 + q2;
                    int c0 = cc - csub;
                    int ra = mq * 32 + m * 16 + g, rb = ra + 8;
                    obase[c0 * 132 + ra]       = acc[m][nt][0] + bias[768 + cc]     + xf[cc * 132 + ra];
                    obase[(c0 + 1) * 132 + ra] = acc[m][nt][1] + bias[768 + cc + 1] + xf[(cc + 1) * 132 + ra];
                    obase[c0 * 132 + rb]       = acc[m][nt][2] + bias[768 + cc]     + xf[cc * 132 + rb];
                    obase[(c0 + 1) * 132 + rb] = acc[m][nt][3] + bias[768 + cc + 1] + xf[(cc + 1) * 132 + rb];
                }
        }
        __syncthreads();  // outs visible; xf fully read -> prefetch can land

        // ---- prefetch next window + Wq + Wk BEFORE the store ----
        const bool more = (w + GRID < NWIN);
        if (more) {
            load_x(x, w + GRID, s_xf, tid);          // group: x
            stage_w(g_win, s_w, tid);
            stage_w(g_win + 16384, s_ks, tid);
            CPC();                                   // group: Wq+Wk
        }

        // ---- store from outs (qs/ab overlays) ----
        float* ob = out + (size_t)b * 128 * 262144;
#pragma unroll
        for (int it = 0; it < 4; it++) {
            int idx = it * 512 + tid;
            int c = idx >> 5, rem = idx & 31;
            int win = rem >> 4, row = rem & 15;
            int dd = row >> 2, hh = row & 3;
            *(float4*)(ob + (size_t)c * 262144 + (size_t)(d0 + dd) * 4096 +
                       (h0 + hh) * 64 + wp + win * 4) =
                *(float4*)(outs_lo + c * 132 + win * 64 + row * 4);
        }
#pragma unroll
        for (int it = 4; it < 8; it++) {
            int idx = it * 512 + tid;
            int c = idx >> 5, rem = idx & 31;
            int win = rem >> 4, row = rem & 15;
            int dd = row >> 2, hh = row & 3;
            *(float4*)(ob + (size_t)c * 262144 + (size_t)(d0 + dd) * 4096 +
                       (h0 + hh) * 64 + wp + win * 4) =
                *(float4*)(outs_hi + (c - 64) * 132 + win * 64 + row * 4);
        }
        if (more) CPW(1);  // next x done (Wq+Wk waited after next LN)
        __syncthreads();   // outs reads done; xf ready for next LN
    }
}

extern "C" void kernel_launch(void* const* d_in, const int* in_sizes, int n_in,
                              void* d_out, int out_size) {
    const float* x      = (const float*)d_in[0];
    const float* ln_g   = (const float*)d_in[1];
    const float* ln_b   = (const float*)d_in[2];
    const float* in_w   = (const float*)d_in[3];
    const float* in_b   = (const float*)d_in[4];
    const float* out_w  = (const float*)d_in[5];
    const float* out_b  = (const float*)d_in[6];
    const float* conv_w = (const float*)d_in[7];
    const float* conv_b = (const float*)d_in[8];
    float* out = (float*)d_out;

    convert_weights_kernel<<<192, 256>>>(in_w, out_w, conv_w);

    cudaFuncSetAttribute(fused_wsa3d_kernel,
                         cudaFuncAttributeMaxDynamicSharedMemorySize, SMEM_BYTES);
    fused_wsa3d_kernel<<<GRID, 512, SMEM_BYTES>>>(x, ln_g, ln_b, in_b, out_b,
                                                  conv_b, out);
}